// round 16
// baseline (speedup 1.0000x reference)
#include <cuda_runtime.h>
#include <math.h>

#define Dm 1024
#define Cc 512
#define Kk 64
#define FBn 513

// Scratch (no allocation allowed) — recomputed every launch, deterministic.
__device__ float2 g_Wc[Dm * Kk];          // 512 KB; aliased as W2[1024][128]
__device__ float  g_FW1p[4][Kk * Dm];     // 1 MB FW1 split-j partials
__device__ float  g_C[Kk][9];             // score-polynomial coefficients
__device__ float  g_Sp[8][1024][128];     // 4 MB spectrum split-K partials

__device__ __constant__ float c_poly[9] = {
    0.0f, 0.5f, 0.3989422804f, 0.0f, -0.0664903801f,
    0.0f, 0.0099735570f, 0.0f, -0.0011873155f };
__device__ __constant__ float c_binom[9][9] = {
    {1,0,0,0,0,0,0,0,0},
    {1,1,0,0,0,0,0,0,0},
    {1,2,1,0,0,0,0,0,0},
    {1,3,3,1,0,0,0,0,0},
    {1,4,6,4,1,0,0,0,0},
    {1,5,10,10,5,1,0,0,0},
    {1,6,15,20,15,6,1,0,0},
    {1,7,21,35,35,21,7,1,0},
    {1,8,28,56,70,56,28,8,1} };

// ---- packed f32x2 helpers (each half is an exact fma.rn.f32) ----
__device__ __forceinline__ unsigned long long pack2(float x, float y) {
    unsigned long long r;
    asm("mov.b64 %0, {%1, %2};"
        : "=l"(r) : "r"(__float_as_uint(x)), "r"(__float_as_uint(y)));
    return r;
}
__device__ __forceinline__ float2 unpack2(unsigned long long v) {
    unsigned int lo, hi;
    asm("mov.b64 {%0, %1}, %2;" : "=r"(lo), "=r"(hi) : "l"(v));
    return make_float2(__uint_as_float(lo), __uint_as_float(hi));
}
#define FMA2(d, a, b) \
    asm("fma.rn.f32x2 %0, %1, %2, %0;" : "+l"(d) : "l"(a), "l"(b))

// ---------------------------------------------------------------------------
// Level-1 merged kernel: grid 256 x 256 threads.
//   blocks [0,128):   FW1 split-j partials  (F @ w1), packed FFMA2
//   blocks [128,256): W build (rotation recurrence, 2 k per thread)
// ---------------------------------------------------------------------------
__global__ __launch_bounds__(256) void prep_a(const float* __restrict__ P,
                                              const float* __restrict__ F,
                                              const float* __restrict__ w1) {
    __shared__ __align__(16) unsigned char sraw[8208];
    const int tid = threadIdx.x;

    if (blockIdx.x < 128) {
        // ---- FW1 partial: FW1p[jq] = F[k0..k0+8) rows @ w1[j-slice] ----
        float4 (*Fs)[2] = (float4(*)[2])sraw;    // [256][2]; float4 = 2 pairs
        const int bid = blockIdx.x;
        const int dq  = bid & 3, kg = (bid >> 2) & 7, jq = bid >> 5;
        const int d   = dq * 256 + tid;
        const int k0  = kg * 8;
        const int j0  = jq * 256;

        for (int idx = tid; idx < 512; idx += 256) {
            int jj = idx >> 1, h = idx & 1;
            Fs[jj][h] = make_float4(F[(k0 + 4*h + 0) * Dm + j0 + jj],
                                    F[(k0 + 4*h + 1) * Dm + j0 + jj],
                                    F[(k0 + 4*h + 2) * Dm + j0 + jj],
                                    F[(k0 + 4*h + 3) * Dm + j0 + jj]);
        }
        __syncthreads();

        unsigned long long A01 = 0ull, A23 = 0ull, A45 = 0ull, A67 = 0ull;
        for (int jj = 0; jj < 256; jj++) {
            float w = w1[(j0 + jj) * Dm + d];
            unsigned long long wp = pack2(w, w);
            ulonglong2 fa = *(const ulonglong2*)&Fs[jj][0];  // (F_k0,F_k1),(F_k2,F_k3)
            ulonglong2 fb = *(const ulonglong2*)&Fs[jj][1];
            FMA2(A01, fa.x, wp);
            FMA2(A23, fa.y, wp);
            FMA2(A45, fb.x, wp);
            FMA2(A67, fb.y, wp);
        }
        float2 p01 = unpack2(A01), p23 = unpack2(A23);
        float2 p45 = unpack2(A45), p67 = unpack2(A67);
        float* o = &g_FW1p[jq][k0 * Dm + d];
        o[0*Dm] = p01.x; o[1*Dm] = p01.y; o[2*Dm] = p23.x; o[3*Dm] = p23.y;
        o[4*Dm] = p45.x; o[5*Dm] = p45.y; o[6*Dm] = p67.x; o[7*Dm] = p67.y;
    } else {
        // ---- build_W: rotation recurrence, thread owns d, 2 k-cols ----
        float2* Ps = (float2*)sraw;              // [FBn] = 4104 B
        const int b  = blockIdx.x - 128;         // 0..127
        const int dq = b & 3, kg = b >> 2;       // 4 dq x 32 kg
        const int d  = dq * 256 + tid;
        const int k0 = kg * 2;

        for (int f = tid; f < FBn; f += 256)
            Ps[f] = *(const float2*)(P + f * Kk + k0);
        __syncthreads();

        float th = -6.283185307179586f * (float)d * (1.0f / 1024.0f);
        float sd, cd;
        sincosf(th, &sd, &cd);

        float c = 1.0f, s = 0.0f;
        float ar0 = 0.f, ar1 = 0.f;
        float ai0 = 0.f, ai1 = 0.f;
        for (int f = 0; f < FBn; f++) {
            float2 p = Ps[f];
            ar0 = fmaf(c, p.x, ar0); ai0 = fmaf(s, p.x, ai0);
            ar1 = fmaf(c, p.y, ar1); ai1 = fmaf(s, p.y, ai1);
            float cn = fmaf(c, cd, -s * sd);
            float sn = fmaf(s, cd,  c * sd);
            c = cn; s = sn;
        }
        g_Wc[d * Kk + k0 + 0] = make_float2(ar0, ai0);
        g_Wc[d * Kk + k0 + 1] = make_float2(ar1, ai1);
    }
}

// ---------------------------------------------------------------------------
// Level-2 merged kernel: grid 192 x 256 threads.
//   blocks [0,128):  spectrum split-K GEMM tile (tokens @ W2), packed FFMA2,
//                    X tile staged PRE-PACKED as (x,x) u64 pairs
//   blocks [128,192): score-polynomial coefficients (one k per block)
// ---------------------------------------------------------------------------
__global__ __launch_bounds__(256) void prep_b(const float* __restrict__ tokens,
                                              const float* __restrict__ b1,
                                              const float* __restrict__ w2) {
    __shared__ __align__(16) unsigned char sraw[33792];
    const int tid = threadIdx.x;

    if (blockIdx.x < 128) {
        // ---- spec_gemm: 64 rows x 128 cols over a 128-d slice ----
        // Xp[row][dd] = packed (x,x); pitch 34 u64 = 272 B:
        //   16B-aligned rows; 4-row read distance = 272 words = bank+16 →
        //   the warp's two distinct LDS.64 addresses are conflict-free.
        unsigned long long (*Xp)[34] = (unsigned long long(*)[34])sraw; // 17408 B
        float (*Ws)[128] = (float(*)[128])(sraw + 17408);               // 16384 B
        const int r0  = (blockIdx.x & 15) * 64;
        const int d0  = (blockIdx.x >> 4) * 128;
        const int ry  = tid >> 4;
        const int cx  = tid & 15;
        const float* W2 = (const float*)g_Wc;   // [1024][128]

        // acc2[r][q] = packed cols (2q, 2q+1) of output row ry*4+r
        unsigned long long acc2[4][4];
#pragma unroll
        for (int r = 0; r < 4; r++)
#pragma unroll
            for (int q = 0; q < 4; q++) acc2[r][q] = 0ull;

        for (int ch = 0; ch < 4; ch++) {
            int db = d0 + ch * 32;
            // X tile: 512 float4 reads, stored duplicated as u64 pairs
            for (int i = tid; i < 64 * 8; i += 256) {
                int rr = i >> 3, dv = (i & 7) * 4;
                float4 v = *(const float4*)(tokens + (size_t)(r0 + rr) * Dm + db + dv);
                ulonglong2 p0 = make_ulonglong2(pack2(v.x, v.x), pack2(v.y, v.y));
                ulonglong2 p1 = make_ulonglong2(pack2(v.z, v.z), pack2(v.w, v.w));
                *(ulonglong2*)&Xp[rr][dv]     = p0;
                *(ulonglong2*)&Xp[rr][dv + 2] = p1;
            }
            // W tile: 32 d x 128 cols = 32*32 float4
            for (int i = tid; i < 32 * 32; i += 256) {
                int rr = i >> 5, cc = i & 31;
                ((float4*)Ws[rr])[cc] =
                    ((const float4*)(W2 + (size_t)(db + rr) * 128))[cc];
            }
            __syncthreads();
#pragma unroll 4
            for (int dd = 0; dd < 32; dd++) {
                // cols cx*8 .. cx*8+7 as 4 packed pairs (memory-adjacent)
                ulonglong2 wA = *(const ulonglong2*)&Ws[dd][cx * 8];
                ulonglong2 wB = *(const ulonglong2*)&Ws[dd][cx * 8 + 4];
#pragma unroll
                for (int r = 0; r < 4; r++) {
                    unsigned long long x2 = Xp[ry * 4 + r][dd];   // LDS.64
                    FMA2(acc2[r][0], x2, wA.x);
                    FMA2(acc2[r][1], x2, wA.y);
                    FMA2(acc2[r][2], x2, wB.x);
                    FMA2(acc2[r][3], x2, wB.y);
                }
            }
            __syncthreads();
        }
#pragma unroll
        for (int r = 0; r < 4; r++) {
            float* o = &g_Sp[blockIdx.x >> 4][r0 + ry * 4 + r][cx * 8];
            *(ulonglong2*)(o)     = make_ulonglong2(acc2[r][0], acc2[r][1]);
            *(ulonglong2*)(o + 4) = make_ulonglong2(acc2[r][2], acc2[r][3]);
        }
    } else {
        // ---- score_coeffs for k = blockIdx.x - 128 ----
        float* red = (float*)sraw;               // [256]
        const int k = blockIdx.x - 128;

        float c[9];
#pragma unroll
        for (int j = 0; j < 9; j++) c[j] = 0.f;

        for (int d = tid; d < Dm; d += 256) {
            int o = k * Dm + d;
            float a = g_FW1p[0][o] + g_FW1p[1][o] + g_FW1p[2][o] + g_FW1p[3][o];
            float b = b1[d];
            float w = w2[d];
            float apow = 1.0f;
#pragma unroll
            for (int j = 0; j < 9; j++) {
                float t = 0.f;
                float bpow = 1.0f;
#pragma unroll
                for (int n = j; n < 9; n++) {
                    t = fmaf(c_poly[n] * c_binom[n][j], bpow, t);
                    bpow *= b;
                }
                c[j] = fmaf(w * apow, t, c[j]);
                apow *= a;
            }
        }
#pragma unroll
        for (int j = 0; j < 9; j++) {
            red[tid] = c[j];
            __syncthreads();
            for (int off = 128; off; off >>= 1) {
                if (tid < off) red[tid] += red[tid + off];
                __syncthreads();
            }
            if (tid == 0) g_C[k][j] = red[0];
            __syncthreads();
        }
    }
}

// ---------------------------------------------------------------------------
// Fused tail: split-K reduce + mask/filter + Horner score + softmax +
// pooled = coeff @ F accumulated in-register onto tokens (packed FFMA2)
// + LayerNorm. grid 128 (8 rows per block), 256 threads.
// Split-K reduce: thread owns 1 row x 2 adjacent k (float4 partial reads).
// ---------------------------------------------------------------------------
#define RW 8
__global__ __launch_bounds__(256) void main_fused(
    const float* __restrict__ tokens, const float* __restrict__ thr_p,
    const float* __restrict__ g_r, const float* __restrict__ g_i,
    const float* __restrict__ l_r, const float* __restrict__ l_i,
    const float* __restrict__ F,
    const float* __restrict__ gamma, const float* __restrict__ beta,
    float* __restrict__ out)
{
    __shared__ float fr_sh[RW][64];
    __shared__ float sc_sh[RW][64];
    __shared__ __align__(16) float coeff_sh[RW][64];
    __shared__ float redbuf[RW][16];
    __shared__ float stats[RW][2];

    const int row0 = blockIdx.x * RW;
    const int tid  = threadIdx.x;
    const int w    = tid >> 5;
    const int lane = tid & 31;

    // ---- residual accumulators = token values, packed pairs (d,d+1),(d+2,d+3)
    unsigned long long a2[RW][2];
#pragma unroll
    for (int r = 0; r < RW; r++) {
        ulonglong2 t = ((const ulonglong2*)(tokens + (size_t)(row0 + r) * Dm))[tid];
        a2[r][0] = t.x; a2[r][1] = t.y;
    }

    // ---- split-K reduce + filter + Horner score ----
    // thread owns row lrow = tid>>5 and k pair (2kp, 2kp+1), kp = tid&31
    {
        const int kp   = tid & 31;
        const int lrow = tid >> 5;           // 0..7
        const int row  = row0 + lrow;
        const float thr = *thr_p;

        float re0 = 0.f, im0 = 0.f, re1 = 0.f, im1 = 0.f;
#pragma unroll
        for (int z = 0; z < 8; z++) {
            float4 p = ((const float4*)g_Sp[z][row])[kp];  // (re0,im0,re1,im1)
            re0 += p.x; im0 += p.y; re1 += p.z; im1 += p.w;
        }
        const int c = row & (Cc - 1);
        float2 grv = *(const float2*)(g_r + c * Kk + 2 * kp);
        float2 giv = *(const float2*)(g_i + c * Kk + 2 * kp);
        float2 lrv = *(const float2*)(l_r + c * Kk + 2 * kp);
        float2 liv = *(const float2*)(l_i + c * Kk + 2 * kp);

        float gr0 = grv.x, gi0 = giv.x;
        if (re0 * re0 + im0 * im0 > thr) { gr0 += lrv.x; gi0 += liv.x; }
        float fr0 = re0 * gr0 - im0 * gi0;             // filtered.real, k=2kp
        float gr1 = grv.y, gi1 = giv.y;
        if (re1 * re1 + im1 * im1 > thr) { gr1 += lrv.y; gi1 += liv.y; }
        float fr1 = re1 * gr1 - im1 * gi1;             // filtered.real, k=2kp+1

        fr_sh[lrow][2 * kp]     = fr0;
        fr_sh[lrow][2 * kp + 1] = fr1;

        const float* C0 = g_C[2 * kp];
        const float* C1 = g_C[2 * kp + 1];
        float s0 = C0[8], s1 = C1[8];
#pragma unroll
        for (int j = 7; j >= 0; j--) {
            s0 = fmaf(s0, fr0, C0[j]);
            s1 = fmaf(s1, fr1, C1[j]);
        }
        sc_sh[lrow][2 * kp]     = s0;    // +b2 softmax-invariant
        sc_sh[lrow][2 * kp + 1] = s1;
    }
    __syncthreads();

    // ---- softmax over k; warp w owns row w; coeff = weight * fr ----
    {
        float s0 = sc_sh[w][lane], s1v = sc_sh[w][lane + 32];
        float m = fmaxf(s0, s1v);
#pragma unroll
        for (int off = 16; off; off >>= 1)
            m = fmaxf(m, __shfl_xor_sync(0xffffffffu, m, off));
        float e0 = expf(s0 - m), e1 = expf(s1v - m);
        float sum = e0 + e1;
#pragma unroll
        for (int off = 16; off; off >>= 1)
            sum += __shfl_xor_sync(0xffffffffu, sum, off);
        float inv = 1.0f / sum;
        coeff_sh[w][lane]      = e0 * inv * fr_sh[w][lane];
        coeff_sh[w][lane + 32] = e1 * inv * fr_sh[w][lane + 32];
    }
    __syncthreads();

    // ---- pooled = coeff @ F accumulated onto a2 (thread = 4 d) ----
    {
        const ulonglong2* F8 = (const ulonglong2*)F;   // pairs of F row-slices
#pragma unroll 2
        for (int kk = 0; kk < Kk; kk += 4) {
            ulonglong2 f0 = F8[(kk + 0) * 256 + tid];
            ulonglong2 f1 = F8[(kk + 1) * 256 + tid];
            ulonglong2 f2 = F8[(kk + 2) * 256 + tid];
            ulonglong2 f3 = F8[(kk + 3) * 256 + tid];
#pragma unroll
            for (int r = 0; r < RW; r++) {
                float4 c4 = *(const float4*)&coeff_sh[r][kk];
                unsigned long long cp;
                cp = pack2(c4.x, c4.x);
                FMA2(a2[r][0], cp, f0.x);
                FMA2(a2[r][1], cp, f0.y);
                cp = pack2(c4.y, c4.y);
                FMA2(a2[r][0], cp, f1.x);
                FMA2(a2[r][1], cp, f1.y);
                cp = pack2(c4.z, c4.z);
                FMA2(a2[r][0], cp, f2.x);
                FMA2(a2[r][1], cp, f2.y);
                cp = pack2(c4.w, c4.w);
                FMA2(a2[r][0], cp, f3.x);
                FMA2(a2[r][1], cp, f3.y);
            }
        }
    }

    // ---- unpack + LayerNorm stats (per row over 1024 = 256 threads x 4) ----
    float4 acc[RW];
    float s1[RW], s2[RW];
#pragma unroll
    for (int r = 0; r < RW; r++) {
        float2 lo = unpack2(a2[r][0]);
        float2 hi = unpack2(a2[r][1]);
        acc[r] = make_float4(lo.x, lo.y, hi.x, hi.y);
        s1[r] = (lo.x + lo.y) + (hi.x + hi.y);
        s2[r] = fmaf(lo.x, lo.x, fmaf(lo.y, lo.y, fmaf(hi.x, hi.x, hi.y * hi.y)));
    }
#pragma unroll
    for (int r = 0; r < RW; r++) {
        float a = s1[r], bq = s2[r];
#pragma unroll
        for (int off = 16; off; off >>= 1) {
            a  += __shfl_xor_sync(0xffffffffu, a, off);
            bq += __shfl_xor_sync(0xffffffffu, bq, off);
        }
        if (lane == 0) { redbuf[r][w] = a; redbuf[r][8 + w] = bq; }
    }
    __syncthreads();
    if (tid < RW) {
        float t1 = 0.f, t2 = 0.f;
#pragma unroll
        for (int i = 0; i < 8; i++) { t1 += redbuf[tid][i]; t2 += redbuf[tid][8 + i]; }
        float mean = t1 * (1.0f / 1024.0f);
        float var  = t2 * (1.0f / 1024.0f) - mean * mean;
        stats[tid][0] = mean;
        stats[tid][1] = rsqrtf(var + 1e-5f);
    }
    __syncthreads();

    // ---- normalize + affine + store (float4) ----
    {
        float4 gm = ((const float4*)gamma)[tid];
        float4 bt = ((const float4*)beta)[tid];
#pragma unroll
        for (int r = 0; r < RW; r++) {
            float mean = stats[r][0], rstd = stats[r][1];
            float4 o;
            o.x = (acc[r].x - mean) * rstd * gm.x + bt.x;
            o.y = (acc[r].y - mean) * rstd * gm.y + bt.y;
            o.z = (acc[r].z - mean) * rstd * gm.z + bt.z;
            o.w = (acc[r].w - mean) * rstd * gm.w + bt.w;
            ((float4*)(out + (size_t)(row0 + r) * Dm))[tid] = o;
        }
    }
}

// ---------------------------------------------------------------------------
extern "C" void kernel_launch(void* const* d_in, const int* in_sizes, int n_in,
                              void* d_out, int out_size) {
    const float* tokens = (const float*)d_in[0];
    const float* thr    = (const float*)d_in[1];
    const float* P      = (const float*)d_in[2];   // dsp_projection (FB,K)
    const float* gr     = (const float*)d_in[3];
    const float* gi     = (const float*)d_in[4];
    const float* lr     = (const float*)d_in[5];
    const float* li     = (const float*)d_in[6];
    const float* F      = (const float*)d_in[7];   // frequency_embedding (K,D)
    const float* w1     = (const float*)d_in[8];
    const float* b1     = (const float*)d_in[9];
    const float* w2     = (const float*)d_in[10];
    // d_in[11] = b2: softmax-invariant, unused.
    const float* gamma  = (const float*)d_in[12];
    const float* beta   = (const float*)d_in[13];
    float* out = (float*)d_out;

    prep_a<<<256, 256>>>(P, F, w1);          // level 1: W + FW1 partials
    prep_b<<<192, 256>>>(tokens, b1, w2);    // level 2: spectrum + score coeffs
    main_fused<<<128, 256>>>(tokens, thr, gr, gi, lr, li, F,
                             gamma, beta, out);
}

// round 17
// speedup vs baseline: 1.5767x; 1.5767x over previous
#include <cuda_runtime.h>
#include <math.h>

#define Dm 1024
#define Cc 512
#define Kk 64
#define FBn 513

// Scratch (no allocation allowed) — recomputed every launch, deterministic.
__device__ float2 g_Wc[Dm * Kk];          // 512 KB; aliased as W2[1024][128]
__device__ float  g_FW1p[8][Kk * Dm];     // 2 MB FW1 split-j partials
__device__ float  g_C[Kk][9];             // score-polynomial coefficients
__device__ float  g_Sp[8][1024][128];     // 4 MB spectrum split-K partials

__device__ __constant__ float c_poly[9] = {
    0.0f, 0.5f, 0.3989422804f, 0.0f, -0.0664903801f,
    0.0f, 0.0099735570f, 0.0f, -0.0011873155f };
__device__ __constant__ float c_binom[9][9] = {
    {1,0,0,0,0,0,0,0,0},
    {1,1,0,0,0,0,0,0,0},
    {1,2,1,0,0,0,0,0,0},
    {1,3,3,1,0,0,0,0,0},
    {1,4,6,4,1,0,0,0,0},
    {1,5,10,10,5,1,0,0,0},
    {1,6,15,20,15,6,1,0,0},
    {1,7,21,35,35,21,7,1,0},
    {1,8,28,56,70,56,28,8,1} };

// ---- packed f32x2 helpers (each half is an exact fma.rn.f32) ----
__device__ __forceinline__ unsigned long long pack2(float x, float y) {
    unsigned long long r;
    asm("mov.b64 %0, {%1, %2};"
        : "=l"(r) : "r"(__float_as_uint(x)), "r"(__float_as_uint(y)));
    return r;
}
__device__ __forceinline__ float2 unpack2(unsigned long long v) {
    unsigned int lo, hi;
    asm("mov.b64 {%0, %1}, %2;" : "=r"(lo), "=r"(hi) : "l"(v));
    return make_float2(__uint_as_float(lo), __uint_as_float(hi));
}
#define FMA2(d, a, b) \
    asm("fma.rn.f32x2 %0, %1, %2, %0;" : "+l"(d) : "l"(a), "l"(b))

// ---------------------------------------------------------------------------
// Level-1 merged kernel: grid 384 x 256 threads.
//   blocks [0,256):   FW1 split-j partials  (F @ w1), MLP=8 batched loads
//   blocks [256,384): W build (rotation recurrence, 2 interleaved chains)
// ---------------------------------------------------------------------------
__global__ __launch_bounds__(256) void prep_a(const float* __restrict__ P,
                                              const float* __restrict__ F,
                                              const float* __restrict__ w1) {
    __shared__ __align__(16) unsigned char sraw[8208];
    const int tid = threadIdx.x;

    if (blockIdx.x < 256) {
        // ---- FW1 partial: FW1p[jq] = F[k0..k0+8) rows @ w1[j-slice of 128] --
        float4 (*Fs)[2] = (float4(*)[2])sraw;    // [128][2]; float4 = 2 pairs
        const int bid = blockIdx.x;
        const int dq  = bid & 3, kg = (bid >> 2) & 7, jq = bid >> 5;  // jq 0..7
        const int d   = dq * 256 + tid;
        const int k0  = kg * 8;
        const int j0  = jq * 128;

        {   // stage F rows: 128 j x 2 half-groups = 256 float4, 1 per thread
            int jj = tid >> 1, h = tid & 1;
            Fs[jj][h] = make_float4(F[(k0 + 4*h + 0) * Dm + j0 + jj],
                                    F[(k0 + 4*h + 1) * Dm + j0 + jj],
                                    F[(k0 + 4*h + 2) * Dm + j0 + jj],
                                    F[(k0 + 4*h + 3) * Dm + j0 + jj]);
        }
        __syncthreads();

        unsigned long long A01 = 0ull, A23 = 0ull, A45 = 0ull, A67 = 0ull;
        const float* wbase = w1 + (size_t)j0 * Dm + d;
        for (int jj = 0; jj < 128; jj += 8) {
            float w[8];                      // 8 independent LDGs -> MLP=8
#pragma unroll
            for (int u = 0; u < 8; u++)
                w[u] = wbase[(size_t)(jj + u) * Dm];
#pragma unroll
            for (int u = 0; u < 8; u++) {
                unsigned long long wp = pack2(w[u], w[u]);
                ulonglong2 fa = *(const ulonglong2*)&Fs[jj + u][0];
                ulonglong2 fb = *(const ulonglong2*)&Fs[jj + u][1];
                FMA2(A01, fa.x, wp);
                FMA2(A23, fa.y, wp);
                FMA2(A45, fb.x, wp);
                FMA2(A67, fb.y, wp);
            }
        }
        float2 p01 = unpack2(A01), p23 = unpack2(A23);
        float2 p45 = unpack2(A45), p67 = unpack2(A67);
        float* o = &g_FW1p[jq][k0 * Dm + d];
        o[0*Dm] = p01.x; o[1*Dm] = p01.y; o[2*Dm] = p23.x; o[3*Dm] = p23.y;
        o[4*Dm] = p45.x; o[5*Dm] = p45.y; o[6*Dm] = p67.x; o[7*Dm] = p67.y;
    } else {
        // ---- build_W: 2 interleaved phasor chains (even/odd f, step 2θ) ----
        float2* Ps = (float2*)sraw;              // [FBn] = 4104 B
        const int b  = blockIdx.x - 256;         // 0..127
        const int dq = b & 3, kg = b >> 2;       // 4 dq x 32 kg
        const int d  = dq * 256 + tid;
        const int k0 = kg * 2;

        for (int f = tid; f < FBn; f += 256)
            Ps[f] = *(const float2*)(P + f * Kk + k0);
        __syncthreads();

        float th = -6.283185307179586f * (float)d * (1.0f / 1024.0f);
        float sd, cd;
        sincosf(th, &sd, &cd);
        // double-angle step for both chains
        float cd2 = fmaf(cd, cd, -sd * sd);
        float sd2 = 2.0f * sd * cd;

        float ce = 1.0f, se = 0.0f;    // chain over even f (starts f=0)
        float co = cd,  so = sd;       // chain over odd  f (starts f=1)
        float er0 = 0.f, er1 = 0.f, ei0 = 0.f, ei1 = 0.f;
        float or0 = 0.f, or1 = 0.f, oi0 = 0.f, oi1 = 0.f;
        for (int f = 0; f < 512; f += 2) {
            float2 pe = Ps[f];
            float2 po = Ps[f + 1];
            er0 = fmaf(ce, pe.x, er0); ei0 = fmaf(se, pe.x, ei0);
            er1 = fmaf(ce, pe.y, er1); ei1 = fmaf(se, pe.y, ei1);
            or0 = fmaf(co, po.x, or0); oi0 = fmaf(so, po.x, oi0);
            or1 = fmaf(co, po.y, or1); oi1 = fmaf(so, po.y, oi1);
            float cen = fmaf(ce, cd2, -se * sd2);
            float sen = fmaf(se, cd2,  ce * sd2);
            float con = fmaf(co, cd2, -so * sd2);
            float son = fmaf(so, cd2,  co * sd2);
            ce = cen; se = sen; co = con; so = son;
        }
        {   // final even element f=512 (chain ce/se is now at f=512)
            float2 p = Ps[512];
            er0 = fmaf(ce, p.x, er0); ei0 = fmaf(se, p.x, ei0);
            er1 = fmaf(ce, p.y, er1); ei1 = fmaf(se, p.y, ei1);
        }
        g_Wc[d * Kk + k0 + 0] = make_float2(er0 + or0, ei0 + oi0);
        g_Wc[d * Kk + k0 + 1] = make_float2(er1 + or1, ei1 + oi1);
    }
}

// ---------------------------------------------------------------------------
// Level-2 merged kernel: grid 192 x 256 threads.
//   blocks [0,128):  spectrum split-K GEMM tile (tokens @ W2), packed FFMA2,
//                    X tile staged PRE-PACKED as (x,x) u64 pairs
//   blocks [128,192): score-polynomial coefficients (one k per block)
// ---------------------------------------------------------------------------
__global__ __launch_bounds__(256) void prep_b(const float* __restrict__ tokens,
                                              const float* __restrict__ b1,
                                              const float* __restrict__ w2) {
    __shared__ __align__(16) unsigned char sraw[33792];
    const int tid = threadIdx.x;

    if (blockIdx.x < 128) {
        // ---- spec_gemm: 64 rows x 128 cols over a 128-d slice ----
        unsigned long long (*Xp)[34] = (unsigned long long(*)[34])sraw; // 17408 B
        float (*Ws)[128] = (float(*)[128])(sraw + 17408);               // 16384 B
        const int r0  = (blockIdx.x & 15) * 64;
        const int d0  = (blockIdx.x >> 4) * 128;
        const int ry  = tid >> 4;
        const int cx  = tid & 15;
        const float* W2 = (const float*)g_Wc;   // [1024][128]

        unsigned long long acc2[4][4];
#pragma unroll
        for (int r = 0; r < 4; r++)
#pragma unroll
            for (int q = 0; q < 4; q++) acc2[r][q] = 0ull;

        for (int ch = 0; ch < 4; ch++) {
            int db = d0 + ch * 32;
            for (int i = tid; i < 64 * 8; i += 256) {
                int rr = i >> 3, dv = (i & 7) * 4;
                float4 v = *(const float4*)(tokens + (size_t)(r0 + rr) * Dm + db + dv);
                ulonglong2 p0 = make_ulonglong2(pack2(v.x, v.x), pack2(v.y, v.y));
                ulonglong2 p1 = make_ulonglong2(pack2(v.z, v.z), pack2(v.w, v.w));
                *(ulonglong2*)&Xp[rr][dv]     = p0;
                *(ulonglong2*)&Xp[rr][dv + 2] = p1;
            }
            for (int i = tid; i < 32 * 32; i += 256) {
                int rr = i >> 5, cc = i & 31;
                ((float4*)Ws[rr])[cc] =
                    ((const float4*)(W2 + (size_t)(db + rr) * 128))[cc];
            }
            __syncthreads();
#pragma unroll 4
            for (int dd = 0; dd < 32; dd++) {
                ulonglong2 wA = *(const ulonglong2*)&Ws[dd][cx * 8];
                ulonglong2 wB = *(const ulonglong2*)&Ws[dd][cx * 8 + 4];
#pragma unroll
                for (int r = 0; r < 4; r++) {
                    unsigned long long x2 = Xp[ry * 4 + r][dd];   // LDS.64
                    FMA2(acc2[r][0], x2, wA.x);
                    FMA2(acc2[r][1], x2, wA.y);
                    FMA2(acc2[r][2], x2, wB.x);
                    FMA2(acc2[r][3], x2, wB.y);
                }
            }
            __syncthreads();
        }
#pragma unroll
        for (int r = 0; r < 4; r++) {
            float* o = &g_Sp[blockIdx.x >> 4][r0 + ry * 4 + r][cx * 8];
            *(ulonglong2*)(o)     = make_ulonglong2(acc2[r][0], acc2[r][1]);
            *(ulonglong2*)(o + 4) = make_ulonglong2(acc2[r][2], acc2[r][3]);
        }
    } else {
        // ---- score_coeffs for k = blockIdx.x - 128 ----
        float* red = (float*)sraw;               // [256]
        const int k = blockIdx.x - 128;

        float c[9];
#pragma unroll
        for (int j = 0; j < 9; j++) c[j] = 0.f;

        for (int d = tid; d < Dm; d += 256) {
            int o = k * Dm + d;
            float a = 0.f;                       // 8 independent loads, MLP=8
#pragma unroll
            for (int z = 0; z < 8; z++) a += g_FW1p[z][o];
            float b = b1[d];
            float w = w2[d];
            float apow = 1.0f;
#pragma unroll
            for (int j = 0; j < 9; j++) {
                float t = 0.f;
                float bpow = 1.0f;
#pragma unroll
                for (int n = j; n < 9; n++) {
                    t = fmaf(c_poly[n] * c_binom[n][j], bpow, t);
                    bpow *= b;
                }
                c[j] = fmaf(w * apow, t, c[j]);
                apow *= a;
            }
        }
#pragma unroll
        for (int j = 0; j < 9; j++) {
            red[tid] = c[j];
            __syncthreads();
            for (int off = 128; off; off >>= 1) {
                if (tid < off) red[tid] += red[tid + off];
                __syncthreads();
            }
            if (tid == 0) g_C[k][j] = red[0];
            __syncthreads();
        }
    }
}

// ---------------------------------------------------------------------------
// Fused tail: split-K reduce + mask/filter + Horner score + softmax +
// pooled = coeff @ F accumulated in-register onto tokens (packed FFMA2)
// + LayerNorm. grid 128 (8 rows per block), 256 threads.
// ---------------------------------------------------------------------------
#define RW 8
__global__ __launch_bounds__(256) void main_fused(
    const float* __restrict__ tokens, const float* __restrict__ thr_p,
    const float* __restrict__ g_r, const float* __restrict__ g_i,
    const float* __restrict__ l_r, const float* __restrict__ l_i,
    const float* __restrict__ F,
    const float* __restrict__ gamma, const float* __restrict__ beta,
    float* __restrict__ out)
{
    __shared__ float fr_sh[RW][64];
    __shared__ float sc_sh[RW][64];
    __shared__ __align__(16) float coeff_sh[RW][64];
    __shared__ float redbuf[RW][16];
    __shared__ float stats[RW][2];

    const int row0 = blockIdx.x * RW;
    const int tid  = threadIdx.x;
    const int w    = tid >> 5;
    const int lane = tid & 31;

    unsigned long long a2[RW][2];
#pragma unroll
    for (int r = 0; r < RW; r++) {
        ulonglong2 t = ((const ulonglong2*)(tokens + (size_t)(row0 + r) * Dm))[tid];
        a2[r][0] = t.x; a2[r][1] = t.y;
    }

    // ---- split-K reduce + filter + Horner score ----
    {
        const int kp   = tid & 31;
        const int lrow = tid >> 5;           // 0..7
        const int row  = row0 + lrow;
        const float thr = *thr_p;

        float re0 = 0.f, im0 = 0.f, re1 = 0.f, im1 = 0.f;
#pragma unroll
        for (int z = 0; z < 8; z++) {
            float4 p = ((const float4*)g_Sp[z][row])[kp];  // (re0,im0,re1,im1)
            re0 += p.x; im0 += p.y; re1 += p.z; im1 += p.w;
        }
        const int c = row & (Cc - 1);
        float2 grv = *(const float2*)(g_r + c * Kk + 2 * kp);
        float2 giv = *(const float2*)(g_i + c * Kk + 2 * kp);
        float2 lrv = *(const float2*)(l_r + c * Kk + 2 * kp);
        float2 liv = *(const float2*)(l_i + c * Kk + 2 * kp);

        float gr0 = grv.x, gi0 = giv.x;
        if (re0 * re0 + im0 * im0 > thr) { gr0 += lrv.x; gi0 += liv.x; }
        float fr0 = re0 * gr0 - im0 * gi0;
        float gr1 = grv.y, gi1 = giv.y;
        if (re1 * re1 + im1 * im1 > thr) { gr1 += lrv.y; gi1 += liv.y; }
        float fr1 = re1 * gr1 - im1 * gi1;

        fr_sh[lrow][2 * kp]     = fr0;
        fr_sh[lrow][2 * kp + 1] = fr1;

        const float* C0 = g_C[2 * kp];
        const float* C1 = g_C[2 * kp + 1];
        float s0 = C0[8], s1 = C1[8];
#pragma unroll
        for (int j = 7; j >= 0; j--) {
            s0 = fmaf(s0, fr0, C0[j]);
            s1 = fmaf(s1, fr1, C1[j]);
        }
        sc_sh[lrow][2 * kp]     = s0;    // +b2 softmax-invariant
        sc_sh[lrow][2 * kp + 1] = s1;
    }
    __syncthreads();

    // ---- softmax over k; warp w owns row w; coeff = weight * fr ----
    {
        float s0 = sc_sh[w][lane], s1v = sc_sh[w][lane + 32];
        float m = fmaxf(s0, s1v);
#pragma unroll
        for (int off = 16; off; off >>= 1)
            m = fmaxf(m, __shfl_xor_sync(0xffffffffu, m, off));
        float e0 = expf(s0 - m), e1 = expf(s1v - m);
        float sum = e0 + e1;
#pragma unroll
        for (int off = 16; off; off >>= 1)
            sum += __shfl_xor_sync(0xffffffffu, sum, off);
        float inv = 1.0f / sum;
        coeff_sh[w][lane]      = e0 * inv * fr_sh[w][lane];
        coeff_sh[w][lane + 32] = e1 * inv * fr_sh[w][lane + 32];
    }
    __syncthreads();

    // ---- pooled = coeff @ F accumulated onto a2 (thread = 4 d) ----
    {
        const ulonglong2* F8 = (const ulonglong2*)F;
#pragma unroll 2
        for (int kk = 0; kk < Kk; kk += 4) {
            ulonglong2 f0 = F8[(kk + 0) * 256 + tid];
            ulonglong2 f1 = F8[(kk + 1) * 256 + tid];
            ulonglong2 f2 = F8[(kk + 2) * 256 + tid];
            ulonglong2 f3 = F8[(kk + 3) * 256 + tid];
#pragma unroll
            for (int r = 0; r < RW; r++) {
                float4 c4 = *(const float4*)&coeff_sh[r][kk];
                unsigned long long cp;
                cp = pack2(c4.x, c4.x);
                FMA2(a2[r][0], cp, f0.x);
                FMA2(a2[r][1], cp, f0.y);
                cp = pack2(c4.y, c4.y);
                FMA2(a2[r][0], cp, f1.x);
                FMA2(a2[r][1], cp, f1.y);
                cp = pack2(c4.z, c4.z);
                FMA2(a2[r][0], cp, f2.x);
                FMA2(a2[r][1], cp, f2.y);
                cp = pack2(c4.w, c4.w);
                FMA2(a2[r][0], cp, f3.x);
                FMA2(a2[r][1], cp, f3.y);
            }
        }
    }

    // ---- unpack + LayerNorm stats ----
    float4 acc[RW];
    float s1[RW], s2[RW];
#pragma unroll
    for (int r = 0; r < RW; r++) {
        float2 lo = unpack2(a2[r][0]);
        float2 hi = unpack2(a2[r][1]);
        acc[r] = make_float4(lo.x, lo.y, hi.x, hi.y);
        s1[r] = (lo.x + lo.y) + (hi.x + hi.y);
        s2[r] = fmaf(lo.x, lo.x, fmaf(lo.y, lo.y, fmaf(hi.x, hi.x, hi.y * hi.y)));
    }
#pragma unroll
    for (int r = 0; r < RW; r++) {
        float a = s1[r], bq = s2[r];
#pragma unroll
        for (int off = 16; off; off >>= 1) {
            a  += __shfl_xor_sync(0xffffffffu, a, off);
            bq += __shfl_xor_sync(0xffffffffu, bq, off);
        }
        if (lane == 0) { redbuf[r][w] = a; redbuf[r][8 + w] = bq; }
    }
    __syncthreads();
    if (tid < RW) {
        float t1 = 0.f, t2 = 0.f;
#pragma unroll
        for (int i = 0; i < 8; i++) { t1 += redbuf[tid][i]; t2 += redbuf[tid][8 + i]; }
        float mean = t1 * (1.0f / 1024.0f);
        float var  = t2 * (1.0f / 1024.0f) - mean * mean;
        stats[tid][0] = mean;
        stats[tid][1] = rsqrtf(var + 1e-5f);
    }
    __syncthreads();

    {
        float4 gm = ((const float4*)gamma)[tid];
        float4 bt = ((const float4*)beta)[tid];
#pragma unroll
        for (int r = 0; r < RW; r++) {
            float mean = stats[r][0], rstd = stats[r][1];
            float4 o;
            o.x = (acc[r].x - mean) * rstd * gm.x + bt.x;
            o.y = (acc[r].y - mean) * rstd * gm.y + bt.y;
            o.z = (acc[r].z - mean) * rstd * gm.z + bt.z;
            o.w = (acc[r].w - mean) * rstd * gm.w + bt.w;
            ((float4*)(out + (size_t)(row0 + r) * Dm))[tid] = o;
        }
    }
}

// ---------------------------------------------------------------------------
extern "C" void kernel_launch(void* const* d_in, const int* in_sizes, int n_in,
                              void* d_out, int out_size) {
    const float* tokens = (const float*)d_in[0];
    const float* thr    = (const float*)d_in[1];
    const float* P      = (const float*)d_in[2];   // dsp_projection (FB,K)
    const float* gr     = (const float*)d_in[3];
    const float* gi     = (const float*)d_in[4];
    const float* lr     = (const float*)d_in[5];
    const float* li     = (const float*)d_in[6];
    const float* F      = (const float*)d_in[7];   // frequency_embedding (K,D)
    const float* w1     = (const float*)d_in[8];
    const float* b1     = (const float*)d_in[9];
    const float* w2     = (const float*)d_in[10];
    // d_in[11] = b2: softmax-invariant, unused.
    const float* gamma  = (const float*)d_in[12];
    const float* beta   = (const float*)d_in[13];
    float* out = (float*)d_out;

    prep_a<<<384, 256>>>(P, F, w1);          // level 1: W + FW1 partials
    prep_b<<<192, 256>>>(tokens, b1, w2);    // level 2: spectrum + score coeffs
    main_fused<<<128, 256>>>(tokens, thr, gr, gi, lr, li, F,
                             gamma, beta, out);
}